// round 16
// baseline (speedup 1.0000x reference)
#include <cuda_runtime.h>
#include <cuda_fp16.h>
#include <math.h>
#include <stdint.h>

#define N_NODES 50000
#define N_EDGES 800000
#define DIM 128
#define CAP 64

// Scratch (allocation-free rule: __device__ globals). Zero-initialized at load.
// g_cnt / g_ovf_cnt are zeroed by k_gemm each call (before k_bucket fills them).
__device__ float g_support[N_NODES * DIM];
__device__ int   g_cnt[N_NODES];
__device__ int2  g_bucket[N_NODES * CAP];
__device__ int   g_ovf[N_EDGES];
__device__ int   g_ovf_cnt;

// m16n8k16 row.col fp16 MMA, f32 accumulate-in-place
__device__ __forceinline__ void mma_f16(float* d, const uint32_t* a, uint32_t b0, uint32_t b1) {
    asm volatile(
        "mma.sync.aligned.m16n8k16.row.col.f32.f16.f16.f32 "
        "{%0,%1,%2,%3}, {%4,%5,%6,%7}, {%8,%9}, {%0,%1,%2,%3};"
        : "+f"(d[0]), "+f"(d[1]), "+f"(d[2]), "+f"(d[3])
        : "r"(a[0]), "r"(a[1]), "r"(a[2]), "r"(a[3]), "r"(b0), "r"(b1));
}
__device__ __forceinline__ uint32_t pkh(float a, float b) {
    __half2 h = __floats2half2_rn(a, b);
    return *(uint32_t*)&h;
}

// ---------------- K1: fp16 W-split HMMA GEMM, 256-row tile -------------------
// 256x128 tile, 256 thr, 8 warps, warp tile 64m x 64n (mt=4 -> 2x ILP vs R14).
// B-convert prologue amortized over 2x rows; 196 blocks = 1.3 waves.
#define GEMM_BLOCKS 196            // ceil(50000/256); 196*256 >= N_NODES
#define XS 136                     // fp16 row stride (conflict-free fragments)
#define SMEM_GEMM ((256 + 128 + 128) * XS * 2)   // Xh + Bh + Bl = 139264 B

__global__ __launch_bounds__(256, 1) void k_gemm(const float* __restrict__ X,
                                                 const float* __restrict__ W) {
    extern __shared__ __half sm[];
    __half* Xh = sm;                       // [m][k], 256 rows, XS stride
    __half* Bh = sm + 256 * XS;            // Wt hi: [n][k]
    __half* Bl = sm + (256 + 128) * XS;    // Wt lo

    const int tid   = threadIdx.x;
    const int rbase = blockIdx.x * 256;

    // fused: zero bucket counters (196*256 = 50176 >= N_NODES)
    {
        int gg = blockIdx.x * 256 + tid;
        if (gg < N_NODES) g_cnt[gg] = 0;
        if (gg == 0) g_ovf_cnt = 0;
    }

    // W -> Bh/Bl transposed
    for (int idx = tid; idx < 128 * 128; idx += 256) {
        int k = idx >> 7, n = idx & 127;
        float w = W[idx];
        __half hi = __float2half_rn(w);
        Bh[n * XS + k] = hi;
        Bl[n * XS + k] = __float2half_rn(w - __half2float(hi));
    }
    // X -> Xh (fp16), coalesced float4 loads: 256 rows x 32 float4
    for (int f = tid; f < 256 * 32; f += 256) {
        int r = f >> 5, q = f & 31;
        int row = rbase + r;
        float4 v = make_float4(0.f, 0.f, 0.f, 0.f);
        if (row < N_NODES) v = ((const float4*)X)[row * 32 + q];
        *(uint2*)&Xh[r * XS + q * 4] = make_uint2(pkh(v.x, v.y), pkh(v.z, v.w));
    }
    __syncthreads();

    const int warp = tid >> 5, lane = tid & 31;
    const int g = lane >> 2, tig = lane & 3;
    const int wm = warp & 3;               // m offset = wm*64
    const int wn = warp >> 2;              // n offset = wn*64

    float acc[4][8][4];
    #pragma unroll
    for (int mt = 0; mt < 4; mt++)
        #pragma unroll
        for (int nt = 0; nt < 8; nt++)
            #pragma unroll
            for (int j = 0; j < 4; j++) acc[mt][nt][j] = 0.f;

    for (int ks = 0; ks < 8; ks++) {
        const int kb = ks * 16 + tig * 2;
        uint32_t ah[4][4];
        #pragma unroll
        for (int mt = 0; mt < 4; mt++) {
            int r0 = wm * 64 + mt * 16 + g;
            ah[mt][0] = *(uint32_t*)&Xh[ r0      * XS + kb    ];
            ah[mt][1] = *(uint32_t*)&Xh[(r0 + 8) * XS + kb    ];
            ah[mt][2] = *(uint32_t*)&Xh[ r0      * XS + kb + 8];
            ah[mt][3] = *(uint32_t*)&Xh[(r0 + 8) * XS + kb + 8];
        }
        #pragma unroll
        for (int nt = 0; nt < 8; nt++) {
            int n0 = wn * 64 + nt * 8 + g;
            uint32_t bh0 = *(uint32_t*)&Bh[n0 * XS + kb    ];
            uint32_t bh1 = *(uint32_t*)&Bh[n0 * XS + kb + 8];
            uint32_t bl0 = *(uint32_t*)&Bl[n0 * XS + kb    ];
            uint32_t bl1 = *(uint32_t*)&Bl[n0 * XS + kb + 8];
            #pragma unroll
            for (int mt = 0; mt < 4; mt++) {
                mma_f16(acc[mt][nt], ah[mt], bh0, bh1);
                mma_f16(acc[mt][nt], ah[mt], bl0, bl1);
            }
        }
    }

    #pragma unroll
    for (int mt = 0; mt < 4; mt++) {
        #pragma unroll
        for (int nt = 0; nt < 8; nt++) {
            int row = rbase + wm * 64 + mt * 16 + g;
            int col = wn * 64 + nt * 8 + tig * 2;
            if (row < N_NODES)
                *(float2*)&g_support[row * DIM + col] =
                    make_float2(acc[mt][nt][0], acc[mt][nt][1]);
            if (row + 8 < N_NODES)
                *(float2*)&g_support[(row + 8) * DIM + col] =
                    make_float2(acc[mt][nt][2], acc[mt][nt][3]);
        }
    }
}

// ---------------- K2: bucket edges by destination row ----------------
__global__ void k_bucket(const int* __restrict__ rows,
                         const int* __restrict__ cols,
                         const float* __restrict__ vals) {
    int e = blockIdx.x * blockDim.x + threadIdx.x;
    if (e >= N_EDGES) return;
    int r = rows[e];
    int pos = atomicAdd(&g_cnt[r], 1);
    if (pos < CAP) {
        g_bucket[r * CAP + pos] = make_int2(cols[e], __float_as_int(vals[e]));
    } else {
        int o = atomicAdd(&g_ovf_cnt, 1);
        g_ovf[o] = e;   // correct fallback path (expected empty)
    }
}

// ---------------- K3: warp-per-row aggregate + inline overflow + bias/ELU ----
__global__ __launch_bounds__(256) void k_agg(const float* __restrict__ X,
                                             const float* __restrict__ alpha,
                                             const float* __restrict__ bias,
                                             const int* __restrict__ rows,
                                             const int* __restrict__ cols,
                                             const float* __restrict__ vals,
                                             float* __restrict__ out) {
    int row  = (blockIdx.x * blockDim.x + threadIdx.x) >> 5;
    int lane = threadIdx.x & 31;
    if (row >= N_NODES) return;

    float a0 = alpha[0], a1 = alpha[1];
    float mx = fmaxf(a0, a1);
    float e0 = __expf(a0 - mx), e1 = __expf(a1 - mx);
    float g0 = e0 / (e0 + e1);
    float g1 = e1 / (e0 + e1);

    float4 x4 = ((const float4*)X)[row * 32 + lane];
    float4 acc = make_float4(g1 * x4.x, g1 * x4.y, g1 * x4.z, g1 * x4.w);

    int nraw = g_cnt[row];
    int n = nraw > CAP ? CAP : nraw;
    const int2* bk = g_bucket + row * CAP;
    const float4* sup4 = (const float4*)g_support;

    for (int base = 0; base < n; base += 32) {
        int2 meta = make_int2(0, 0);
        if (base + lane < n) meta = bk[base + lane];
        int cnt = n - base; if (cnt > 32) cnt = 32;
        int c4 = (cnt + 3) & ~3;
        for (int j = 0; j < c4; j += 4) {
            int   c0 = __shfl_sync(0xffffffffu, meta.x, j + 0);
            int   c1 = __shfl_sync(0xffffffffu, meta.x, j + 1);
            int   c2 = __shfl_sync(0xffffffffu, meta.x, j + 2);
            int   c3 = __shfl_sync(0xffffffffu, meta.x, j + 3);
            float v0 = g0 * __int_as_float(__shfl_sync(0xffffffffu, meta.y, j + 0));
            float v1 = g0 * __int_as_float(__shfl_sync(0xffffffffu, meta.y, j + 1));
            float v2 = g0 * __int_as_float(__shfl_sync(0xffffffffu, meta.y, j + 2));
            float v3 = g0 * __int_as_float(__shfl_sync(0xffffffffu, meta.y, j + 3));
            float4 s0 = sup4[c0 * 32 + lane];
            float4 s1 = sup4[c1 * 32 + lane];
            float4 s2 = sup4[c2 * 32 + lane];
            float4 s3 = sup4[c3 * 32 + lane];
            acc.x += v0 * s0.x; acc.y += v0 * s0.y; acc.z += v0 * s0.z; acc.w += v0 * s0.w;
            acc.x += v1 * s1.x; acc.y += v1 * s1.y; acc.z += v1 * s1.z; acc.w += v1 * s1.w;
            acc.x += v2 * s2.x; acc.y += v2 * s2.y; acc.z += v2 * s2.z; acc.w += v2 * s2.w;
            acc.x += v3 * s3.x; acc.y += v3 * s3.y; acc.z += v3 * s3.z; acc.w += v3 * s3.w;
        }
    }

    // inline overflow fallback: scan global overflow list (expected 0 entries)
    if (nraw > CAP) {
        int nov = g_ovf_cnt;
        for (int i = 0; i < nov; i++) {
            int e = g_ovf[i];
            if (rows[e] == row) {
                int c = cols[e];
                float v = g0 * vals[e];
                float4 s = sup4[c * 32 + lane];
                acc.x += v * s.x; acc.y += v * s.y; acc.z += v * s.z; acc.w += v * s.w;
            }
        }
    }

    // bias + ELU (unconditional; all contributions in-register)
    float4 b = ((const float4*)bias)[lane];
    acc.x += b.x; acc.y += b.y; acc.z += b.z; acc.w += b.w;
    acc.x = acc.x > 0.f ? acc.x : expm1f(acc.x);
    acc.y = acc.y > 0.f ? acc.y : expm1f(acc.y);
    acc.z = acc.z > 0.f ? acc.z : expm1f(acc.z);
    acc.w = acc.w > 0.f ? acc.w : expm1f(acc.w);
    ((float4*)out)[row * 32 + lane] = acc;
}

extern "C" void kernel_launch(void* const* d_in, const int* in_sizes, int n_in,
                              void* d_out, int out_size) {
    const float* X     = (const float*)d_in[0];
    const float* W     = (const float*)d_in[1];
    const float* bias  = (const float*)d_in[2];
    const float* alpha = (const float*)d_in[3];
    const float* vals  = (const float*)d_in[4];
    const int*   rows  = (const int*)d_in[5];
    const int*   cols  = (const int*)d_in[6];
    float* out = (float*)d_out;

    static bool attr_set = false;
    if (!attr_set) {
        cudaFuncSetAttribute(k_gemm, cudaFuncAttributeMaxDynamicSharedMemorySize, SMEM_GEMM);
        attr_set = true;
    }

    k_gemm  <<<GEMM_BLOCKS, 256, SMEM_GEMM>>>(X, W);
    k_bucket<<<(N_EDGES + 255) / 256, 256>>>(rows, cols, vals);
    k_agg   <<<(N_NODES + 7) / 8, 256>>>(X, alpha, bias, rows, cols, vals, out);
}

// round 17
// speedup vs baseline: 1.0274x; 1.0274x over previous
#include <cuda_runtime.h>
#include <cuda_fp16.h>
#include <math.h>
#include <stdint.h>

#define N_NODES 50000
#define N_EDGES 800000
#define DIM 128
#define CAP 64

// Scratch (allocation-free rule: __device__ globals). Zero-initialized at load.
// g_cnt / g_ovf_cnt are zeroed by k_gemm each call (before k_bucket fills them).
__device__ float g_support[N_NODES * DIM];
__device__ int   g_cnt[N_NODES];
__device__ int2  g_bucket[N_NODES * CAP];
__device__ int   g_ovf[N_EDGES];
__device__ int   g_ovf_cnt;

// m16n8k16 row.col fp16 MMA, f32 accumulate-in-place
__device__ __forceinline__ void mma_f16(float* d, const uint32_t* a, uint32_t b0, uint32_t b1) {
    asm volatile(
        "mma.sync.aligned.m16n8k16.row.col.f32.f16.f16.f32 "
        "{%0,%1,%2,%3}, {%4,%5,%6,%7}, {%8,%9}, {%0,%1,%2,%3};"
        : "+f"(d[0]), "+f"(d[1]), "+f"(d[2]), "+f"(d[3])
        : "r"(a[0]), "r"(a[1]), "r"(a[2]), "r"(a[3]), "r"(b0), "r"(b1));
}
__device__ __forceinline__ uint32_t pkh(float a, float b) {
    __half2 h = __floats2half2_rn(a, b);
    return *(uint32_t*)&h;
}

// ---------------- K1: fp16 W-split HMMA GEMM, 256-row tile, 512 threads ------
// 256x128 tile, 512 thr, 16 warps (8m x 2n), warp tile 32m x 64n (= R14's
// proven per-warp shape). 16 warps/SM = 4/SMSP -> 2x latency coverage vs R16.
#define GEMM_BLOCKS 196            // ceil(50000/256); 196*512 >= N_NODES
#define GEMM_THREADS 512
#define XS 136                     // fp16 row stride (conflict-free fragments)
#define SMEM_GEMM ((256 + 128 + 128) * XS * 2)   // Xh + Bh + Bl = 139264 B

__global__ __launch_bounds__(GEMM_THREADS, 1) void k_gemm(const float* __restrict__ X,
                                                          const float* __restrict__ W) {
    extern __shared__ __half sm[];
    __half* Xh = sm;                       // [m][k], 256 rows, XS stride
    __half* Bh = sm + 256 * XS;            // Wt hi: [n][k]
    __half* Bl = sm + (256 + 128) * XS;    // Wt lo

    const int tid   = threadIdx.x;
    const int rbase = blockIdx.x * 256;

    // fused: zero bucket counters (196*512 = 100352 >= N_NODES)
    {
        int gg = blockIdx.x * GEMM_THREADS + tid;
        if (gg < N_NODES) g_cnt[gg] = 0;
        if (gg == 0) g_ovf_cnt = 0;
    }

    // W -> Bh/Bl transposed
    for (int idx = tid; idx < 128 * 128; idx += GEMM_THREADS) {
        int k = idx >> 7, n = idx & 127;
        float w = W[idx];
        __half hi = __float2half_rn(w);
        Bh[n * XS + k] = hi;
        Bl[n * XS + k] = __float2half_rn(w - __half2float(hi));
    }
    // X -> Xh (fp16), coalesced float4 loads: 256 rows x 32 float4
    for (int f = tid; f < 256 * 32; f += GEMM_THREADS) {
        int r = f >> 5, q = f & 31;
        int row = rbase + r;
        float4 v = make_float4(0.f, 0.f, 0.f, 0.f);
        if (row < N_NODES) v = ((const float4*)X)[row * 32 + q];
        *(uint2*)&Xh[r * XS + q * 4] = make_uint2(pkh(v.x, v.y), pkh(v.z, v.w));
    }
    __syncthreads();

    const int warp = tid >> 5, lane = tid & 31;
    const int g = lane >> 2, tig = lane & 3;
    const int wm = warp & 7;               // m offset = wm*32 (8 groups)
    const int wn = warp >> 3;              // n offset = wn*64 (2 groups)

    float acc[2][8][4];
    #pragma unroll
    for (int mt = 0; mt < 2; mt++)
        #pragma unroll
        for (int nt = 0; nt < 8; nt++)
            #pragma unroll
            for (int j = 0; j < 4; j++) acc[mt][nt][j] = 0.f;

    #pragma unroll 2
    for (int ks = 0; ks < 8; ks++) {
        const int kb = ks * 16 + tig * 2;
        uint32_t ah[2][4];
        #pragma unroll
        for (int mt = 0; mt < 2; mt++) {
            int r0 = wm * 32 + mt * 16 + g;
            ah[mt][0] = *(uint32_t*)&Xh[ r0      * XS + kb    ];
            ah[mt][1] = *(uint32_t*)&Xh[(r0 + 8) * XS + kb    ];
            ah[mt][2] = *(uint32_t*)&Xh[ r0      * XS + kb + 8];
            ah[mt][3] = *(uint32_t*)&Xh[(r0 + 8) * XS + kb + 8];
        }
        #pragma unroll
        for (int nt = 0; nt < 8; nt++) {
            int n0 = wn * 64 + nt * 8 + g;
            uint32_t bh0 = *(uint32_t*)&Bh[n0 * XS + kb    ];
            uint32_t bh1 = *(uint32_t*)&Bh[n0 * XS + kb + 8];
            uint32_t bl0 = *(uint32_t*)&Bl[n0 * XS + kb    ];
            uint32_t bl1 = *(uint32_t*)&Bl[n0 * XS + kb + 8];
            #pragma unroll
            for (int mt = 0; mt < 2; mt++) {
                mma_f16(acc[mt][nt], ah[mt], bh0, bh1);
                mma_f16(acc[mt][nt], ah[mt], bl0, bl1);
            }
        }
    }

    #pragma unroll
    for (int mt = 0; mt < 2; mt++) {
        #pragma unroll
        for (int nt = 0; nt < 8; nt++) {
            int row = rbase + wm * 32 + mt * 16 + g;
            int col = wn * 64 + nt * 8 + tig * 2;
            if (row < N_NODES)
                *(float2*)&g_support[row * DIM + col] =
                    make_float2(acc[mt][nt][0], acc[mt][nt][1]);
            if (row + 8 < N_NODES)
                *(float2*)&g_support[(row + 8) * DIM + col] =
                    make_float2(acc[mt][nt][2], acc[mt][nt][3]);
        }
    }
}

// ---------------- K2: bucket edges by destination row ----------------
__global__ void k_bucket(const int* __restrict__ rows,
                         const int* __restrict__ cols,
                         const float* __restrict__ vals) {
    int e = blockIdx.x * blockDim.x + threadIdx.x;
    if (e >= N_EDGES) return;
    int r = rows[e];
    int pos = atomicAdd(&g_cnt[r], 1);
    if (pos < CAP) {
        g_bucket[r * CAP + pos] = make_int2(cols[e], __float_as_int(vals[e]));
    } else {
        int o = atomicAdd(&g_ovf_cnt, 1);
        g_ovf[o] = e;   // correct fallback path (expected empty)
    }
}

// ---------------- K3: warp-per-row aggregate + inline overflow + bias/ELU ----
__global__ __launch_bounds__(256) void k_agg(const float* __restrict__ X,
                                             const float* __restrict__ alpha,
                                             const float* __restrict__ bias,
                                             const int* __restrict__ rows,
                                             const int* __restrict__ cols,
                                             const float* __restrict__ vals,
                                             float* __restrict__ out) {
    int row  = (blockIdx.x * blockDim.x + threadIdx.x) >> 5;
    int lane = threadIdx.x & 31;
    if (row >= N_NODES) return;

    float a0 = alpha[0], a1 = alpha[1];
    float mx = fmaxf(a0, a1);
    float e0 = __expf(a0 - mx), e1 = __expf(a1 - mx);
    float g0 = e0 / (e0 + e1);
    float g1 = e1 / (e0 + e1);

    float4 x4 = ((const float4*)X)[row * 32 + lane];
    float4 acc = make_float4(g1 * x4.x, g1 * x4.y, g1 * x4.z, g1 * x4.w);

    int nraw = g_cnt[row];
    int n = nraw > CAP ? CAP : nraw;
    const int2* bk = g_bucket + row * CAP;
    const float4* sup4 = (const float4*)g_support;

    for (int base = 0; base < n; base += 32) {
        int2 meta = make_int2(0, 0);
        if (base + lane < n) meta = bk[base + lane];
        int cnt = n - base; if (cnt > 32) cnt = 32;
        int c4 = (cnt + 3) & ~3;
        for (int j = 0; j < c4; j += 4) {
            int   c0 = __shfl_sync(0xffffffffu, meta.x, j + 0);
            int   c1 = __shfl_sync(0xffffffffu, meta.x, j + 1);
            int   c2 = __shfl_sync(0xffffffffu, meta.x, j + 2);
            int   c3 = __shfl_sync(0xffffffffu, meta.x, j + 3);
            float v0 = g0 * __int_as_float(__shfl_sync(0xffffffffu, meta.y, j + 0));
            float v1 = g0 * __int_as_float(__shfl_sync(0xffffffffu, meta.y, j + 1));
            float v2 = g0 * __int_as_float(__shfl_sync(0xffffffffu, meta.y, j + 2));
            float v3 = g0 * __int_as_float(__shfl_sync(0xffffffffu, meta.y, j + 3));
            float4 s0 = sup4[c0 * 32 + lane];
            float4 s1 = sup4[c1 * 32 + lane];
            float4 s2 = sup4[c2 * 32 + lane];
            float4 s3 = sup4[c3 * 32 + lane];
            acc.x += v0 * s0.x; acc.y += v0 * s0.y; acc.z += v0 * s0.z; acc.w += v0 * s0.w;
            acc.x += v1 * s1.x; acc.y += v1 * s1.y; acc.z += v1 * s1.z; acc.w += v1 * s1.w;
            acc.x += v2 * s2.x; acc.y += v2 * s2.y; acc.z += v2 * s2.z; acc.w += v2 * s2.w;
            acc.x += v3 * s3.x; acc.y += v3 * s3.y; acc.z += v3 * s3.z; acc.w += v3 * s3.w;
        }
    }

    // inline overflow fallback: scan global overflow list (expected 0 entries)
    if (nraw > CAP) {
        int nov = g_ovf_cnt;
        for (int i = 0; i < nov; i++) {
            int e = g_ovf[i];
            if (rows[e] == row) {
                int c = cols[e];
                float v = g0 * vals[e];
                float4 s = sup4[c * 32 + lane];
                acc.x += v * s.x; acc.y += v * s.y; acc.z += v * s.z; acc.w += v * s.w;
            }
        }
    }

    // bias + ELU (unconditional; all contributions in-register)
    float4 b = ((const float4*)bias)[lane];
    acc.x += b.x; acc.y += b.y; acc.z += b.z; acc.w += b.w;
    acc.x = acc.x > 0.f ? acc.x : expm1f(acc.x);
    acc.y = acc.y > 0.f ? acc.y : expm1f(acc.y);
    acc.z = acc.z > 0.f ? acc.z : expm1f(acc.z);
    acc.w = acc.w > 0.f ? acc.w : expm1f(acc.w);
    ((float4*)out)[row * 32 + lane] = acc;
}

extern "C" void kernel_launch(void* const* d_in, const int* in_sizes, int n_in,
                              void* d_out, int out_size) {
    const float* X     = (const float*)d_in[0];
    const float* W     = (const float*)d_in[1];
    const float* bias  = (const float*)d_in[2];
    const float* alpha = (const float*)d_in[3];
    const float* vals  = (const float*)d_in[4];
    const int*   rows  = (const int*)d_in[5];
    const int*   cols  = (const int*)d_in[6];
    float* out = (float*)d_out;

    static bool attr_set = false;
    if (!attr_set) {
        cudaFuncSetAttribute(k_gemm, cudaFuncAttributeMaxDynamicSharedMemorySize, SMEM_GEMM);
        attr_set = true;
    }

    k_gemm  <<<GEMM_BLOCKS, GEMM_THREADS, SMEM_GEMM>>>(X, W);
    k_bucket<<<(N_EDGES + 255) / 256, 256>>>(rows, cols, vals);
    k_agg   <<<(N_NODES + 7) / 8, 256>>>(X, alpha, bias, rows, cols, vals, out);
}